// round 4
// baseline (speedup 1.0000x reference)
#include <cuda_runtime.h>
#include <cuda_fp16.h>
#include <cstdint>

// Problem dims (fixed by dataset)
#define BB 8
#define NN 2048
#define CC 128
#define NQT 16  // NN / 128

// ---------------- scratch (device globals; no allocs allowed) ----------------
__device__ unsigned short g_hn[BB * NN * CC];  // normalized h, fp16, [b][n][c]
__device__ unsigned short g_h[BB * NN * CC];   // h (pre-norm), fp16, [b][n][c]

// ---------------- PTX helpers (sm_80-era family-portable ONLY) ----------------
__device__ __forceinline__ uint32_t smem_u32(const void* p) {
    uint32_t a;
    asm("{ .reg .u64 t; cvta.to.shared.u64 t, %1; cvt.u32.u64 %0, t; }" : "=r"(a) : "l"(p));
    return a;
}

__device__ __forceinline__ void cp_async16(uint32_t dst, const void* src) {
    asm volatile("cp.async.cg.shared.global [%0], [%1], 16;" :: "r"(dst), "l"(src) : "memory");
}
#define CP_COMMIT() asm volatile("cp.async.commit_group;" ::: "memory")
#define CP_WAIT0()  asm volatile("cp.async.wait_group 0;" ::: "memory")

__device__ __forceinline__ void ldsm_x2(uint32_t& r0, uint32_t& r1, uint32_t a) {
    asm volatile("ldmatrix.sync.aligned.m8n8.x2.shared.b16 {%0,%1}, [%2];"
                 : "=r"(r0), "=r"(r1) : "r"(a));
}
__device__ __forceinline__ void ldsm_x2t(uint32_t& r0, uint32_t& r1, uint32_t a) {
    asm volatile("ldmatrix.sync.aligned.m8n8.x2.trans.shared.b16 {%0,%1}, [%2];"
                 : "=r"(r0), "=r"(r1) : "r"(a));
}
__device__ __forceinline__ void ldsm_x4(uint32_t* r, uint32_t a) {
    asm volatile("ldmatrix.sync.aligned.m8n8.x4.shared.b16 {%0,%1,%2,%3}, [%4];"
                 : "=r"(r[0]), "=r"(r[1]), "=r"(r[2]), "=r"(r[3]) : "r"(a));
}

__device__ __forceinline__ void mma16816(float* d, const uint32_t* a, uint32_t b0, uint32_t b1) {
    asm volatile("mma.sync.aligned.m16n8k16.row.col.f32.f16.f16.f32 "
                 "{%0,%1,%2,%3}, {%4,%5,%6,%7}, {%8,%9}, {%0,%1,%2,%3};"
                 : "+f"(d[0]), "+f"(d[1]), "+f"(d[2]), "+f"(d[3])
                 : "r"(a[0]), "r"(a[1]), "r"(a[2]), "r"(a[3]), "r"(b0), "r"(b1));
}

// pack two f32 -> f16x2 (lo = first arg)
__device__ __forceinline__ uint32_t pack_h2(float lo, float hi) {
    uint32_t d;
    asm("cvt.rn.f16x2.f32 %0, %1, %2;" : "=r"(d) : "f"(hi), "f"(lo));
    return d;
}

// ---------------- Kernel 1: Linear + bias + L2-normalize -> fp16 hn & h ----------------
#define K1_WPAD 132
#define K1_SPAD 136
#define K1_SMEM ((128 * K1_WPAD + 32 * 128 + 32 * K1_SPAD) * 4)

__global__ __launch_bounds__(256) void k1_linear_norm(const float* __restrict__ x,
                                                      const float* __restrict__ W,
                                                      const float* __restrict__ bias) {
    extern __shared__ float sm1[];
    float* Ws = sm1;                       // 128 * 132
    float* xs = Ws + 128 * K1_WPAD;        // 32 * 128
    float* st = xs + 32 * 128;             // 32 * 136

    const int b = blockIdx.y;
    const int n0 = blockIdx.x * 32;
    const int tid = threadIdx.x, lane = tid & 31, w = tid >> 5;

    const float* xg = x + ((size_t)b * NN + n0) * CC;

    for (int i = tid; i < 128 * 128; i += 256) Ws[(i >> 7) * K1_WPAD + (i & 127)] = W[i];
    for (int i = tid; i < 32 * 128; i += 256) xs[i] = xg[i];
    __syncthreads();

    // rows {w, w+8, w+16, w+24}, cols {lane, lane+32, lane+64, lane+96}
    float acc[4][4];
#pragma unroll
    for (int j = 0; j < 4; j++)
#pragma unroll
        for (int i = 0; i < 4; i++) acc[j][i] = 0.0f;

#pragma unroll 8
    for (int k4 = 0; k4 < 32; k4++) {
        float4 xa[4], wb[4];
#pragma unroll
        for (int j = 0; j < 4; j++) xa[j] = *(const float4*)&xs[(w + 8 * j) * 128 + 4 * k4];
#pragma unroll
        for (int i = 0; i < 4; i++) wb[i] = *(const float4*)&Ws[(lane + 32 * i) * K1_WPAD + 4 * k4];
#pragma unroll
        for (int j = 0; j < 4; j++)
#pragma unroll
            for (int i = 0; i < 4; i++) {
                acc[j][i] += xa[j].x * wb[i].x;
                acc[j][i] += xa[j].y * wb[i].y;
                acc[j][i] += xa[j].z * wb[i].z;
                acc[j][i] += xa[j].w * wb[i].w;
            }
    }
#pragma unroll
    for (int i = 0; i < 4; i++) {
        float bi = bias[lane + 32 * i];
#pragma unroll
        for (int j = 0; j < 4; j++) acc[j][i] += bi;
    }

    // per-row L2 norm (row lives entirely in one warp)
    float scl[4];
#pragma unroll
    for (int j = 0; j < 4; j++) {
        float s = 0.0f;
#pragma unroll
        for (int i = 0; i < 4; i++) s += acc[j][i] * acc[j][i];
#pragma unroll
        for (int o = 16; o > 0; o >>= 1) s += __shfl_xor_sync(0xFFFFFFFFu, s, o);
        scl[j] = 1.0f / fmaxf(sqrtf(s), 1e-12f);
    }

    // ---- stage hn (fp32), convert+store fp16 coalesced ----
#pragma unroll
    for (int j = 0; j < 4; j++)
#pragma unroll
        for (int i = 0; i < 4; i++)
            st[(w + 8 * j) * K1_SPAD + lane + 32 * i] = acc[j][i] * scl[j];
    __syncthreads();
    {
        __half2* hng = (__half2*)(g_hn + ((size_t)b * NN + n0) * CC);
        for (int i = tid; i < 2048; i += 256) {
            int r = i >> 6, c2 = i & 63;
            hng[r * 64 + c2] = __floats2half2_rn(st[r * K1_SPAD + 2 * c2],
                                                 st[r * K1_SPAD + 2 * c2 + 1]);
        }
    }
    __syncthreads();

    // ---- stage h (fp32), convert+store fp16 coalesced ----
#pragma unroll
    for (int j = 0; j < 4; j++)
#pragma unroll
        for (int i = 0; i < 4; i++)
            st[(w + 8 * j) * K1_SPAD + lane + 32 * i] = acc[j][i];
    __syncthreads();
    {
        __half2* hg = (__half2*)(g_h + ((size_t)b * NN + n0) * CC);
        for (int i = tid; i < 2048; i += 256) {
            int r = i >> 6, c2 = i & 63;
            hg[r * 64 + c2] = __floats2half2_rn(st[r * K1_SPAD + 2 * c2],
                                                st[r * K1_SPAD + 2 * c2 + 1]);
        }
    }
}

// ---------------- Kernel 2: fused S=hn_p.hn_q^T ; gated=edge*S ; O += gated.h_q ----------------
// grid (16,8), 256 threads (8 warps x m16 rows), 1 CTA/SM.
#define TPITCH_H 136                     // halves per tile row (272B, 17x16B)
#define TILE_B (128 * TPITCH_H * 2)      // 34816 B
#define EPITCH 68                        // floats per edge row (272B)
#define ECHUNK_B (128 * EPITCH * 4)      // 34816 B
#define EOFF (4 * TILE_B)                // after 2x2 tiles
#define K2_SMEM (EOFF + 2 * ECHUNK_B)    // 208896 B

// stage one 128x128 fp16 tile (row-major, 256B rows) -> SMEM pitch 272B
__device__ __forceinline__ void stage_tile(const unsigned short* src, char* dst, int tid) {
#pragma unroll
    for (int it = 0; it < 8; it++) {
        int i = tid + it * 256;
        int row = i >> 4, ch = i & 15;
        cp_async16(smem_u32(dst + row * 272 + ch * 16), src + row * 128 + ch * 8);
    }
}
// stage 128 x 64 floats of edge (gmem row pitch NN) -> SMEM pitch 272B
__device__ __forceinline__ void stage_edge(const float* src, char* dst, int tid) {
#pragma unroll
    for (int it = 0; it < 8; it++) {
        int i = tid + it * 256;
        int row = i >> 4, ch = i & 15;
        cp_async16(smem_u32(dst + row * 272 + ch * 16), src + (size_t)row * NN + ch * 4);
    }
}

__global__ __launch_bounds__(256, 1) void k2_fused(const float* __restrict__ edge,
                                                   float* __restrict__ out) {
    extern __shared__ char smc[];
    const int b = blockIdx.y, p = blockIdx.x;
    const int tid = threadIdx.x, wid = tid >> 5, lane = tid & 31;

    const unsigned short* hnb = g_hn + (size_t)b * NN * CC;
    const unsigned short* hb = g_h + (size_t)b * NN * CC;
    const float* eb = edge + ((size_t)b * NN + (size_t)p * 128) * NN;

    char* tl[2][2];
#pragma unroll
    for (int u = 0; u < 2; u++)
#pragma unroll
        for (int v = 0; v < 2; v++) tl[u][v] = smc + (u * 2 + v) * TILE_B;
    float* ebf[2] = {(float*)(smc + EOFF), (float*)(smc + EOFF + ECHUNK_B)};

    // ---- preload A1 fragments (hn_p rows, persistent in registers) ----
    stage_tile(hnb + (size_t)p * 128 * CC, tl[0][0], tid);
    CP_COMMIT();
    CP_WAIT0();
    __syncthreads();

    uint32_t a1f[32];
    {
        uint32_t base = smem_u32(tl[0][0]);
        int row = wid * 16 + (lane & 7) + ((lane & 8) ? 8 : 0);
        uint32_t ra = base + (uint32_t)row * 272 + ((lane & 16) ? 16 : 0);
#pragma unroll
        for (int kk = 0; kk < 8; kk++) ldsm_x4(a1f + 4 * kk, ra + kk * 32);
    }
    __syncthreads();  // everyone has A1; tile(0,0) reusable

    // O accumulators: 16 n-tiles x 4
    float Of[64];
#pragma unroll
    for (int i = 0; i < 64; i++) Of[i] = 0.0f;

    const int erow = wid * 16 + (lane >> 2);
    const int ecol2 = 2 * (lane & 3);

    // pipeline prologue: G_A(0) = tiles(q=0) + edge chunk0(q=0)
    stage_tile(hnb, tl[0][0], tid);
    stage_tile(hb, tl[0][1], tid);
    stage_edge(eb, (char*)ebf[0], tid);
    CP_COMMIT();

    for (int q = 0; q < NQT; q++) {
        const char* bhn = tl[q & 1][0];
        const char* bh = tl[q & 1][1];
        const uint32_t bhn_u = smem_u32(bhn);
        const uint32_t bh_u = smem_u32(bh);

        CP_WAIT0();
        __syncthreads();

        // G_B(q): edge chunk1 of q
        stage_edge(eb + (size_t)q * 128 + 64, (char*)ebf[1], tid);
        CP_COMMIT();

        // ---- halves: h0 uses t 0..3 (j 0..7, edge chunk0); h1 uses t 4..7 ----
#pragma unroll
        for (int half = 0; half < 2; half++) {
            const float* ebuf = ebf[half];
#pragma unroll
            for (int ti = 0; ti < 4; ti++) {
                const int tt = half * 4 + ti;
                float S[2][4];
                uint32_t A2[4];
#pragma unroll
                for (int jj = 0; jj < 2; jj++) {
                    const int j = 2 * tt + jj;
#pragma unroll
                    for (int i = 0; i < 4; i++) S[jj][i] = 0.0f;
                    uint32_t ba = bhn_u + (uint32_t)((j * 8 + (lane & 7)) * 272)
                                + ((lane & 8) ? 16 : 0);
#pragma unroll
                    for (int kk = 0; kk < 8; kk++) {
                        uint32_t b0, b1;
                        ldsm_x2(b0, b1, ba + kk * 32);
                        mma16816(S[jj], a1f + 4 * kk, b0, b1);
                    }
                    const int jl = j & 7;
                    float2 e0 = *(const float2*)&ebuf[erow * EPITCH + jl * 8 + ecol2];
                    float2 e1 = *(const float2*)&ebuf[(erow + 8) * EPITCH + jl * 8 + ecol2];
                    S[jj][0] *= e0.x; S[jj][1] *= e0.y;
                    S[jj][2] *= e1.x; S[jj][3] *= e1.y;
                }
                A2[0] = pack_h2(S[0][0], S[0][1]);
                A2[1] = pack_h2(S[0][2], S[0][3]);
                A2[2] = pack_h2(S[1][0], S[1][1]);
                A2[3] = pack_h2(S[1][2], S[1][3]);

                uint32_t b2a = bh_u + (uint32_t)((16 * tt + (lane & 15)) * 272);
#pragma unroll
                for (int j2 = 0; j2 < 16; j2++) {
                    uint32_t b0, b1;
                    ldsm_x2t(b0, b1, b2a + j2 * 16);
                    mma16816(Of + 4 * j2, A2, b0, b1);
                }
            }

            if (half == 0) {
                // mid-iteration: wait G_B, then prefetch G_A(q+1)
                CP_WAIT0();
                __syncthreads();
                if (q < NQT - 1) {
                    stage_tile(hnb + (size_t)(q + 1) * 128 * CC, tl[(q + 1) & 1][0], tid);
                    stage_tile(hb + (size_t)(q + 1) * 128 * CC, tl[(q + 1) & 1][1], tid);
                    stage_edge(eb + (size_t)(q + 1) * 128, (char*)ebf[0], tid);
                }
                CP_COMMIT();
            }
        }
    }

    // ---- epilogue: ReLU + store ----
    {
        float* ob = out + ((size_t)b * NN + (size_t)p * 128) * CC;
        const int r0 = wid * 16 + (lane >> 2);
#pragma unroll
        for (int j2 = 0; j2 < 16; j2++) {
            const int c = j2 * 8 + ecol2;
            float2 v0, v1;
            v0.x = fmaxf(Of[4 * j2 + 0], 0.0f);
            v0.y = fmaxf(Of[4 * j2 + 1], 0.0f);
            v1.x = fmaxf(Of[4 * j2 + 2], 0.0f);
            v1.y = fmaxf(Of[4 * j2 + 3], 0.0f);
            *(float2*)&ob[(size_t)r0 * CC + c] = v0;
            *(float2*)&ob[(size_t)(r0 + 8) * CC + c] = v1;
        }
    }
}

// ---------------- host launch ----------------
extern "C" void kernel_launch(void* const* d_in, const int* in_sizes, int n_in,
                              void* d_out, int out_size) {
    (void)out_size;
    const float *x = nullptr, *edge = nullptr, *W = nullptr, *bias = nullptr;
    for (int i = 0; i < n_in; i++) {
        int sz = in_sizes[i];
        if (sz == BB * NN * CC) x = (const float*)d_in[i];
        else if (sz == BB * NN * NN) edge = (const float*)d_in[i];
        else if (sz == CC * CC) W = (const float*)d_in[i];
        else if (sz == CC) bias = (const float*)d_in[i];
    }
    if (!x) x = (const float*)d_in[0];
    if (!edge) edge = (const float*)d_in[1];
    if (!W) W = (const float*)d_in[2];
    if (!bias) bias = (const float*)d_in[3];
    float* out = (float*)d_out;

    cudaFuncSetAttribute(k1_linear_norm, cudaFuncAttributeMaxDynamicSharedMemorySize, K1_SMEM);
    cudaFuncSetAttribute(k2_fused, cudaFuncAttributeMaxDynamicSharedMemorySize, K2_SMEM);

    k1_linear_norm<<<dim3(64, 8), 256, K1_SMEM>>>(x, W, bias);
    k2_fused<<<dim3(16, 8), 256, K2_SMEM>>>(edge, out);
}

// round 5
// speedup vs baseline: 1.6316x; 1.6316x over previous
#include <cuda_runtime.h>
#include <cuda_fp16.h>
#include <cstdint>

// Problem dims (fixed by dataset)
#define BB 8
#define NN 2048
#define CC 128
#define NQT 16  // NN / 128

// ---------------- scratch (device globals; no allocs allowed) ----------------
__device__ unsigned short g_hn[BB * NN * CC];  // normalized h, fp16, [b][n][c]
__device__ float g_norm[BB * NN];              // per-row L2 norm of h (fp32)

// ---------------- PTX helpers (family-portable: sm_75/80-era) ----------------
__device__ __forceinline__ uint32_t smem_u32(const void* p) {
    uint32_t a;
    asm("{ .reg .u64 t; cvta.to.shared.u64 t, %1; cvt.u32.u64 %0, t; }" : "=r"(a) : "l"(p));
    return a;
}

__device__ __forceinline__ void cp_async16(uint32_t dst, const void* src) {
    asm volatile("cp.async.cg.shared.global [%0], [%1], 16;" :: "r"(dst), "l"(src) : "memory");
}
#define CP_COMMIT() asm volatile("cp.async.commit_group;" ::: "memory")
#define CP_WAIT0()  asm volatile("cp.async.wait_group 0;" ::: "memory")

__device__ __forceinline__ void ldsm_x4(uint32_t* r, uint32_t a) {
    asm volatile("ldmatrix.sync.aligned.m8n8.x4.shared.b16 {%0,%1,%2,%3}, [%4];"
                 : "=r"(r[0]), "=r"(r[1]), "=r"(r[2]), "=r"(r[3]) : "r"(a));
}
__device__ __forceinline__ void ldsm_x4t(uint32_t* r, uint32_t a) {
    asm volatile("ldmatrix.sync.aligned.m8n8.x4.trans.shared.b16 {%0,%1,%2,%3}, [%4];"
                 : "=r"(r[0]), "=r"(r[1]), "=r"(r[2]), "=r"(r[3]) : "r"(a));
}

__device__ __forceinline__ void mma16816(float* d, const uint32_t* a, uint32_t b0, uint32_t b1) {
    asm volatile("mma.sync.aligned.m16n8k16.row.col.f32.f16.f16.f32 "
                 "{%0,%1,%2,%3}, {%4,%5,%6,%7}, {%8,%9}, {%0,%1,%2,%3};"
                 : "+f"(d[0]), "+f"(d[1]), "+f"(d[2]), "+f"(d[3])
                 : "r"(a[0]), "r"(a[1]), "r"(a[2]), "r"(a[3]), "r"(b0), "r"(b1));
}

// pack two f32 -> f16x2 (lo = first arg)
__device__ __forceinline__ uint32_t pack_h2(float lo, float hi) {
    uint32_t d;
    asm("cvt.rn.f16x2.f32 %0, %1, %2;" : "=r"(d) : "f"(hi), "f"(lo));
    return d;
}

// =====================================================================
// Kernel 1: h = x@W^T + b (fp16 MMA) ; norm = ||h|| ; g_hn = h/norm (fp16)
// grid (16,8), 256 threads (8 warps x m16). SMEM: x-tile + W-tile fp16.
// =====================================================================
#define TILE_B 34816                     // 128 rows * 272B (fp16 tile, padded)
#define K1_SMEM (2 * TILE_B + 512)

__global__ __launch_bounds__(256) void k1_linear_norm(const float* __restrict__ x,
                                                      const float* __restrict__ W,
                                                      const float* __restrict__ bias) {
    extern __shared__ char sm1[];
    char* xs = sm1;                 // x tile fp16 (reused as hn stage later)
    char* Ws = sm1 + TILE_B;        // W tile fp16
    float* bs = (float*)(sm1 + 2 * TILE_B);

    const int b = blockIdx.y;
    const int nb0 = blockIdx.x * 128;
    const int tid = threadIdx.x, wid = tid >> 5, lane = tid & 31;

    // stage x and W (fp32 -> fp16), pitch 272B
    {
        const float* xg = x + ((size_t)b * NN + nb0) * CC;
#pragma unroll
        for (int it = 0; it < 16; it++) {
            int i = tid + it * 256;
            int row = i >> 5, c4 = i & 31;
            float4 v = *(const float4*)(xg + (size_t)row * 128 + c4 * 4);
            *(uint2*)(xs + row * 272 + c4 * 8) = make_uint2(pack_h2(v.x, v.y), pack_h2(v.z, v.w));
            float4 w4 = *(const float4*)(W + (size_t)row * 128 + c4 * 4);
            *(uint2*)(Ws + row * 272 + c4 * 8) = make_uint2(pack_h2(w4.x, w4.y), pack_h2(w4.z, w4.w));
        }
        if (tid < 32) *(float4*)&bs[tid * 4] = *(const float4*)(bias + tid * 4);
    }
    __syncthreads();

    // A fragments: warp's m16 rows of x
    uint32_t af[32];
    {
        uint32_t xa = smem_u32(xs) + (uint32_t)((wid * 16 + (lane & 15)) * 272)
                    + ((lane & 16) ? 16 : 0);
#pragma unroll
        for (int kk = 0; kk < 8; kk++) ldsm_x4(af + 4 * kk, xa + kk * 32);
    }

    float Hf[64];
#pragma unroll
    for (int i = 0; i < 64; i++) Hf[i] = 0.0f;

    // B = W rows (o = n dim), non-trans x4 (n16 x k16 per load)
    {
        uint32_t wb = smem_u32(Ws) + (uint32_t)(((lane & 7) + ((lane & 16) ? 8 : 0)) * 272)
                    + ((lane & 8) ? 16 : 0);
#pragma unroll
        for (int jp = 0; jp < 8; jp++) {
#pragma unroll
            for (int kk = 0; kk < 8; kk++) {
                uint32_t bf[4];
                ldsm_x4(bf, wb + (uint32_t)(jp * 16 * 272) + kk * 32);
                mma16816(Hf + (jp * 2) * 4, af + 4 * kk, bf[0], bf[1]);
                mma16816(Hf + (jp * 2 + 1) * 4, af + 4 * kk, bf[2], bf[3]);
            }
        }
    }

    // bias + row sum-of-squares
    float s0 = 0.0f, s1 = 0.0f;
#pragma unroll
    for (int j = 0; j < 16; j++) {
        float2 bv = *(const float2*)&bs[j * 8 + 2 * (lane & 3)];
        Hf[j * 4 + 0] += bv.x; Hf[j * 4 + 1] += bv.y;
        Hf[j * 4 + 2] += bv.x; Hf[j * 4 + 3] += bv.y;
        s0 += Hf[j * 4 + 0] * Hf[j * 4 + 0] + Hf[j * 4 + 1] * Hf[j * 4 + 1];
        s1 += Hf[j * 4 + 2] * Hf[j * 4 + 2] + Hf[j * 4 + 3] * Hf[j * 4 + 3];
    }
    s0 += __shfl_xor_sync(0xFFFFFFFFu, s0, 1); s0 += __shfl_xor_sync(0xFFFFFFFFu, s0, 2);
    s1 += __shfl_xor_sync(0xFFFFFFFFu, s1, 1); s1 += __shfl_xor_sync(0xFFFFFFFFu, s1, 2);
    float n0 = sqrtf(s0), n1 = sqrtf(s1);
    float i0 = 1.0f / fmaxf(n0, 1e-12f), i1 = 1.0f / fmaxf(n1, 1e-12f);
    if ((lane & 3) == 0) {
        g_norm[(size_t)b * NN + nb0 + wid * 16 + (lane >> 2)] = n0;
        g_norm[(size_t)b * NN + nb0 + wid * 16 + (lane >> 2) + 8] = n1;
    }

    __syncthreads();  // done reading xs; reuse as hn staging
    {
        const int r = wid * 16 + (lane >> 2);
#pragma unroll
        for (int j = 0; j < 16; j++) {
            *(uint32_t*)(xs + r * 272 + j * 16 + 4 * (lane & 3)) =
                pack_h2(Hf[j * 4 + 0] * i0, Hf[j * 4 + 1] * i0);
            *(uint32_t*)(xs + (r + 8) * 272 + j * 16 + 4 * (lane & 3)) =
                pack_h2(Hf[j * 4 + 2] * i1, Hf[j * 4 + 3] * i1);
        }
    }
    __syncthreads();
    {
        unsigned short* hng = g_hn + ((size_t)b * NN + nb0) * CC;
#pragma unroll
        for (int it = 0; it < 8; it++) {
            int i = tid + it * 256;
            int row = i >> 4, ch = i & 15;
            *(float4*)(hng + (size_t)row * 128 + ch * 8) = *(const float4*)(xs + row * 272 + ch * 16);
        }
    }
}

// =====================================================================
// Kernel 2: S = hn_p.hn_q^T ; O += (edge*S*norm_q).hn_q ; ReLU
// grid (16,8), 256 threads: warps (mi=wid&3 -> m32, ni=wid>>2 -> n64/k64 split).
// Per-warp partial O reduced across ni-pair once at the end.
// =====================================================================
#define EPITCH 68                        // floats per edge row (272B)
#define OFF_T 0                          // 2 hn tiles (ping-pong)
#define OFF_E (2 * TILE_B)               // 4 edge chunks: (par*2+c)
#define OFF_N (6 * TILE_B)               // 2 x 128 norm floats
#define K2_SMEM (6 * TILE_B + 1024)      // 209920 B

// stage one 128x128 fp16 tile (row-major, 256B rows) -> SMEM pitch 272B
__device__ __forceinline__ void stage_tile(const unsigned short* src, char* dst, int tid) {
#pragma unroll
    for (int it = 0; it < 8; it++) {
        int i = tid + it * 256;
        int row = i >> 4, ch = i & 15;
        cp_async16(smem_u32(dst + row * 272 + ch * 16), src + (size_t)row * 128 + ch * 8);
    }
}
// stage 128 x 64 floats of edge (gmem row pitch NN) -> SMEM pitch 272B
__device__ __forceinline__ void stage_edge(const float* src, char* dst, int tid) {
#pragma unroll
    for (int it = 0; it < 8; it++) {
        int i = tid + it * 256;
        int row = i >> 4, ch = i & 15;
        cp_async16(smem_u32(dst + row * 272 + ch * 16), src + (size_t)row * NN + ch * 4);
    }
}

__global__ __launch_bounds__(256, 1) void k2_fused(const float* __restrict__ edge,
                                                   float* __restrict__ out) {
    extern __shared__ char smc[];
    const int b = blockIdx.y, p = blockIdx.x;
    const int tid = threadIdx.x, wid = tid >> 5, lane = tid & 31;
    const int mi = wid & 3, ni = wid >> 2;

    const unsigned short* hnb = g_hn + (size_t)b * NN * CC;
    const float* eb = edge + ((size_t)b * NN + (size_t)p * 128) * NN;
    const float* nb = g_norm + (size_t)b * NN;

    // ---- preload A1 fragments (hn_p, m32 per warp) ----
    stage_tile(hnb + (size_t)p * 128 * CC, smc + OFF_T, tid);
    CP_COMMIT(); CP_WAIT0(); __syncthreads();

    uint32_t a1f[2][32];
    {
        uint32_t base = smem_u32(smc + OFF_T);
#pragma unroll
        for (int mt = 0; mt < 2; mt++) {
            uint32_t ra = base + (uint32_t)((mi * 32 + mt * 16 + (lane & 15)) * 272)
                        + ((lane & 16) ? 16 : 0);
#pragma unroll
            for (int kk = 0; kk < 8; kk++) ldsm_x4(a1f[mt] + 4 * kk, ra + kk * 32);
        }
    }
    __syncthreads();  // A1 in regs; tile buf 0 reusable

    float Of[128];
#pragma unroll
    for (int i = 0; i < 128; i++) Of[i] = 0.0f;

    // pipeline prologue: q=0 -> parity 0 buffers
    stage_tile(hnb, smc + OFF_T, tid);
    stage_edge(eb, smc + OFF_E, tid);
    stage_edge(eb + 64, smc + OFF_E + TILE_B, tid);
    if (tid < 32) cp_async16(smem_u32(smc + OFF_N) + tid * 16, nb + tid * 4);
    CP_COMMIT();

    const int r0 = mi * 32 + (lane >> 2);
    const int c0 = 2 * (lane & 3);

    for (int q = 0; q < NQT; q++) {
        const int par = q & 1;
        CP_WAIT0();
        __syncthreads();

        // prefetch q+1 into opposite-parity buffers (spans whole q compute)
        if (q < NQT - 1) {
            const int qn = q + 1, pn = par ^ 1;
            stage_tile(hnb + (size_t)qn * 128 * CC, smc + OFF_T + pn * TILE_B, tid);
            stage_edge(eb + (size_t)qn * 128, smc + OFF_E + (pn * 2 + 0) * TILE_B, tid);
            stage_edge(eb + (size_t)qn * 128 + 64, smc + OFF_E + (pn * 2 + 1) * TILE_B, tid);
            if (tid < 32)
                cp_async16(smem_u32(smc + OFF_N) + pn * 512 + tid * 16, nb + qn * 128 + tid * 4);
        }
        CP_COMMIT();

        const uint32_t tb = smem_u32(smc + OFF_T + par * TILE_B);
        const float* ech = (const float*)(smc + OFF_E + (par * 2 + ni) * TILE_B);
        const float* nch = (const float*)(smc + OFF_N + par * 512) + ni * 64;
        const uint32_t b1base = tb + (uint32_t)((ni * 64 + (lane & 7) + ((lane & 16) ? 8 : 0)) * 272)
                              + ((lane & 8) ? 16 : 0);
        const uint32_t b2base = tb + (uint32_t)((ni * 64 + (lane & 15)) * 272)
                              + ((lane & 16) ? 16 : 0);

#pragma unroll
        for (int tt = 0; tt < 4; tt++) {
            // ---- MMA1: S[m32, n16] over k=128 ----
            float S[16];
#pragma unroll
            for (int i = 0; i < 16; i++) S[i] = 0.0f;
            {
                const uint32_t bb1 = b1base + (uint32_t)(tt * 16 * 272);
#pragma unroll
                for (int kk = 0; kk < 8; kk++) {
                    uint32_t bf[4];
                    ldsm_x4(bf, bb1 + kk * 32);
                    mma16816(S + 0,  a1f[0] + 4 * kk, bf[0], bf[1]);
                    mma16816(S + 4,  a1f[0] + 4 * kk, bf[2], bf[3]);
                    mma16816(S + 8,  a1f[1] + 4 * kk, bf[0], bf[1]);
                    mma16816(S + 12, a1f[1] + 4 * kk, bf[2], bf[3]);
                }
            }
            // ---- gate: S *= edge * norm_q ----
#pragma unroll
            for (int jj = 0; jj < 2; jj++) {
                const int c = tt * 16 + jj * 8 + c0;
                float2 nv = *(const float2*)&nch[c];
#pragma unroll
                for (int mt = 0; mt < 2; mt++) {
                    float2 e0 = *(const float2*)&ech[(r0 + mt * 16) * EPITCH + c];
                    float2 e1 = *(const float2*)&ech[(r0 + mt * 16 + 8) * EPITCH + c];
                    const int si = mt * 8 + jj * 4;
                    S[si + 0] *= e0.x * nv.x; S[si + 1] *= e0.y * nv.y;
                    S[si + 2] *= e1.x * nv.x; S[si + 3] *= e1.y * nv.y;
                }
            }
            // ---- pack A2 (m32 x k16) ----
            uint32_t A2[2][4];
#pragma unroll
            for (int mt = 0; mt < 2; mt++) {
                A2[mt][0] = pack_h2(S[mt * 8 + 0], S[mt * 8 + 1]);
                A2[mt][1] = pack_h2(S[mt * 8 + 2], S[mt * 8 + 3]);
                A2[mt][2] = pack_h2(S[mt * 8 + 4], S[mt * 8 + 5]);
                A2[mt][3] = pack_h2(S[mt * 8 + 6], S[mt * 8 + 7]);
            }
            // ---- MMA2: O[m32, n128] += A2 . hn_q[k16, n128] ----
            {
                const uint32_t bb2 = b2base + (uint32_t)(tt * 16 * 272);
#pragma unroll
                for (int j2p = 0; j2p < 8; j2p++) {
                    uint32_t bf[4];
                    ldsm_x4t(bf, bb2 + j2p * 32);
                    mma16816(Of + (j2p * 2) * 4,       A2[0], bf[0], bf[1]);
                    mma16816(Of + (j2p * 2 + 1) * 4,   A2[0], bf[2], bf[3]);
                    mma16816(Of + 64 + (j2p * 2) * 4,     A2[1], bf[0], bf[1]);
                    mma16816(Of + 64 + (j2p * 2 + 1) * 4, A2[1], bf[2], bf[3]);
                }
            }
        }
    }

    // ---- cross-warp (ni) reduction + ReLU + store ----
    __syncthreads();  // all compute done; edge SMEM reusable
    float* red = (float*)(smc + OFF_E + mi * 16512) + lane * 129;
    if (ni == 1) {
#pragma unroll
        for (int i = 0; i < 128; i++) red[i] = Of[i];
    }
    __syncthreads();
    if (ni == 0) {
#pragma unroll
        for (int i = 0; i < 128; i++) Of[i] += red[i];
        float* ob = out + ((size_t)b * NN + (size_t)p * 128 + mi * 32) * CC;
        const int rr = lane >> 2;
#pragma unroll
        for (int mt = 0; mt < 2; mt++)
#pragma unroll
            for (int j2 = 0; j2 < 16; j2++) {
                const int c = j2 * 8 + c0;
                float2 v0, v1;
                v0.x = fmaxf(Of[mt * 64 + j2 * 4 + 0], 0.0f);
                v0.y = fmaxf(Of[mt * 64 + j2 * 4 + 1], 0.0f);
                v1.x = fmaxf(Of[mt * 64 + j2 * 4 + 2], 0.0f);
                v1.y = fmaxf(Of[mt * 64 + j2 * 4 + 3], 0.0f);
                *(float2*)&ob[(size_t)(mt * 16 + rr) * CC + c] = v0;
                *(float2*)&ob[(size_t)(mt * 16 + rr + 8) * CC + c] = v1;
            }
    }
}

// ---------------- host launch ----------------
extern "C" void kernel_launch(void* const* d_in, const int* in_sizes, int n_in,
                              void* d_out, int out_size) {
    (void)out_size;
    const float *x = nullptr, *edge = nullptr, *W = nullptr, *bias = nullptr;
    for (int i = 0; i < n_in; i++) {
        int sz = in_sizes[i];
        if (sz == BB * NN * CC) x = (const float*)d_in[i];
        else if (sz == BB * NN * NN) edge = (const float*)d_in[i];
        else if (sz == CC * CC) W = (const float*)d_in[i];
        else if (sz == CC) bias = (const float*)d_in[i];
    }
    if (!x) x = (const float*)d_in[0];
    if (!edge) edge = (const float*)d_in[1];
    if (!W) W = (const float*)d_in[2];
    if (!bias) bias = (const float*)d_in[3];
    float* out = (float*)d_out;

    cudaFuncSetAttribute(k1_linear_norm, cudaFuncAttributeMaxDynamicSharedMemorySize, K1_SMEM);
    cudaFuncSetAttribute(k2_fused, cudaFuncAttributeMaxDynamicSharedMemorySize, K2_SMEM);

    k1_linear_norm<<<dim3(16, 8), 256, K1_SMEM>>>(x, W, bias);
    k2_fused<<<dim3(16, 8), 256, K2_SMEM>>>(edge, out);
}